// round 1
// baseline (speedup 1.0000x reference)
#include <cuda_runtime.h>
#include <math.h>

#define B_ 8
#define C_ 64
#define N_ 4096

// Scratch for support = X^T W : [B, N, C] row-major (8 MB)
__device__ float g_support[B_ * N_ * C_];

// -------------------------------------------------------------------------
// support[b, j, c] = sum_k x[b, k, j] * w[k, c]
// One block per (64-wide j tile, batch). 256 threads, 4x4 register microtile.
// -------------------------------------------------------------------------
__global__ __launch_bounds__(256) void support_kernel(const float* __restrict__ x,
                                                      const float* __restrict__ w) {
    __shared__ float ws[C_ * 64];   // ws[k][c]
    __shared__ float xs[C_ * 64];   // xs[k][j]
    const int b  = blockIdx.y;
    const int jb = blockIdx.x * 64;
    const int t  = threadIdx.x;
    const int tx = t & 15, ty = t >> 4;
    const float* xb = x + (size_t)b * C_ * N_;

    for (int idx = t; idx < 1024; idx += 256) {
        ((float4*)ws)[idx] = ((const float4*)w)[idx];
        int k = idx >> 4, f = idx & 15;
        ((float4*)xs)[idx] = *(const float4*)(xb + k * N_ + jb + 4 * f);
    }
    __syncthreads();

    float acc[4][4] = {};
#pragma unroll 8
    for (int k = 0; k < 64; k++) {
        float4 xv = *(float4*)(xs + k * 64 + 4 * ty);
        float4 wv = *(float4*)(ws + k * 64 + 4 * tx);
        float xa[4] = {xv.x, xv.y, xv.z, xv.w};
        float wa[4] = {wv.x, wv.y, wv.z, wv.w};
#pragma unroll
        for (int jj = 0; jj < 4; jj++)
#pragma unroll
            for (int cc = 0; cc < 4; cc++)
                acc[jj][cc] = fmaf(xa[jj], wa[cc], acc[jj][cc]);
    }

    float* sb = g_support + ((size_t)b * N_ + jb) * C_;
#pragma unroll
    for (int jj = 0; jj < 4; jj++) {
        float4 r = make_float4(acc[jj][0], acc[jj][1], acc[jj][2], acc[jj][3]);
        *(float4*)(sb + (4 * ty + jj) * C_ + 4 * tx) = r;
    }
}

// -------------------------------------------------------------------------
// Fused flash attention, fp32:
//   S = Q K  (S_ij = sum_c x[c,i] x[c,j]),  online softmax,  O += P V
//   out[b,c,i] = O[i,c] / l[i] + x[b,c,i]
// One block per (64-row q tile, batch). 256 threads.
// smem: qs[c][i], ks[c][j] (reused as ps[i][j]), vs[j][c]  -> 48 KB total.
// -------------------------------------------------------------------------
__global__ __launch_bounds__(256) void attn_kernel(const float* __restrict__ x,
                                                   float* __restrict__ out) {
    __shared__ float qs[64 * 64];   // [c][i]
    __shared__ float ks[64 * 64];   // [c][j], reused as ps[i][j]
    __shared__ float vs[64 * 64];   // [j][c]

    const int b  = blockIdx.y;
    const int qb = blockIdx.x * 64;
    const int t  = threadIdx.x;
    const int tx = t & 15, ty = t >> 4;
    const float* xb = x + (size_t)b * C_ * N_;
    const float* vb = g_support + (size_t)b * N_ * C_;

    // Load Q tile: qs[c][i] = x[b, c, qb+i]
    for (int idx = t; idx < 1024; idx += 256) {
        int c = idx >> 4, f = idx & 15;
        ((float4*)qs)[idx] = *(const float4*)(xb + c * N_ + qb + 4 * f);
    }

    float o[4][4] = {};
    float m[4] = {-1e30f, -1e30f, -1e30f, -1e30f};
    float l[4] = {};

    for (int kt = 0; kt < N_; kt += 64) {
        __syncthreads();   // previous PV reads of ks/vs done (and Q load barrier on iter 0)
        // Load K tile (ks[c][j]) and V tile (vs[j][c])
        for (int idx = t; idx < 1024; idx += 256) {
            int r = idx >> 4, f = idx & 15;
            ((float4*)ks)[idx] = *(const float4*)(xb + r * N_ + kt + 4 * f);
            ((float4*)vs)[idx] = *(const float4*)(vb + (size_t)(kt + r) * C_ + 4 * f);
        }
        __syncthreads();

        // ---- S = Q K (4x4 microtile per thread) ----
        float s[4][4] = {};
#pragma unroll 8
        for (int c = 0; c < 64; c++) {
            float4 qv = *(float4*)(qs + c * 64 + 4 * ty);
            float4 kv = *(float4*)(ks + c * 64 + 4 * tx);
            float qa[4] = {qv.x, qv.y, qv.z, qv.w};
            float ka[4] = {kv.x, kv.y, kv.z, kv.w};
#pragma unroll
            for (int rr = 0; rr < 4; rr++)
#pragma unroll
                for (int cc = 0; cc < 4; cc++)
                    s[rr][cc] = fmaf(qa[rr], ka[cc], s[rr][cc]);
        }

        // ---- online softmax (row stats across the 16 tx lanes) ----
#pragma unroll
        for (int rr = 0; rr < 4; rr++) {
            float tmax = fmaxf(fmaxf(s[rr][0], s[rr][1]), fmaxf(s[rr][2], s[rr][3]));
#pragma unroll
            for (int off = 8; off > 0; off >>= 1)
                tmax = fmaxf(tmax, __shfl_xor_sync(0xffffffffu, tmax, off));
            float mnew = fmaxf(m[rr], tmax);
            float corr = __expf(m[rr] - mnew);
            float rs = 0.f;
#pragma unroll
            for (int cc = 0; cc < 4; cc++) {
                s[rr][cc] = __expf(s[rr][cc] - mnew);
                rs += s[rr][cc];
            }
#pragma unroll
            for (int off = 8; off > 0; off >>= 1)
                rs += __shfl_xor_sync(0xffffffffu, rs, off);
            l[rr] = l[rr] * corr + rs;
            m[rr] = mnew;
#pragma unroll
            for (int cc = 0; cc < 4; cc++) o[rr][cc] *= corr;
        }

        __syncthreads();   // all S reads of ks complete
        // Stage P into ks buffer as ps[i][j] (row-major, conflict-free STS.128)
#pragma unroll
        for (int rr = 0; rr < 4; rr++) {
            float4 pr = make_float4(s[rr][0], s[rr][1], s[rr][2], s[rr][3]);
            *(float4*)(ks + (4 * ty + rr) * 64 + 4 * tx) = pr;
        }
        __syncthreads();   // P visible

        // ---- O += P V ----
#pragma unroll 4
        for (int j4 = 0; j4 < 16; j4++) {
            float4 pv[4], vv[4];
#pragma unroll
            for (int rr = 0; rr < 4; rr++)
                pv[rr] = *(float4*)(ks + (4 * ty + rr) * 64 + 4 * j4);
#pragma unroll
            for (int jj = 0; jj < 4; jj++)
                vv[jj] = *(float4*)(vs + (4 * j4 + jj) * 64 + 4 * tx);
            float pa[4][4] = {{pv[0].x, pv[0].y, pv[0].z, pv[0].w},
                              {pv[1].x, pv[1].y, pv[1].z, pv[1].w},
                              {pv[2].x, pv[2].y, pv[2].z, pv[2].w},
                              {pv[3].x, pv[3].y, pv[3].z, pv[3].w}};
            float va[4][4] = {{vv[0].x, vv[0].y, vv[0].z, vv[0].w},
                              {vv[1].x, vv[1].y, vv[1].z, vv[1].w},
                              {vv[2].x, vv[2].y, vv[2].z, vv[2].w},
                              {vv[3].x, vv[3].y, vv[3].z, vv[3].w}};
#pragma unroll
            for (int rr = 0; rr < 4; rr++)
#pragma unroll
                for (int jj = 0; jj < 4; jj++)
#pragma unroll
                    for (int cc = 0; cc < 4; cc++)
                        o[rr][cc] = fmaf(pa[rr][jj], va[jj][cc], o[rr][cc]);
        }
    }

    // ---- epilogue: normalize, add residual, scatter to [b, c, i] ----
#pragma unroll
    for (int rr = 0; rr < 4; rr++) {
        float inv = 1.f / l[rr];
        int i = qb + 4 * ty + rr;
#pragma unroll
        for (int cc = 0; cc < 4; cc++) {
            int c = 4 * tx + cc;
            size_t gi = ((size_t)b * C_ + c) * N_ + i;
            out[gi] = o[rr][cc] * inv + xb[(size_t)c * N_ + i];
        }
    }
}

extern "C" void kernel_launch(void* const* d_in, const int* in_sizes, int n_in,
                              void* d_out, int out_size) {
    const float* x = (const float*)d_in[0];   // [8, 64, 64, 64]
    const float* w = (const float*)d_in[1];   // [64, 64]
    float* out = (float*)d_out;

    dim3 grid(N_ / 64, B_);
    support_kernel<<<grid, 256>>>(x, w);
    attn_kernel<<<grid, 256>>>(x, out);
}

// round 3
// speedup vs baseline: 2.0447x; 2.0447x over previous
#include <cuda_runtime.h>
#include <math.h>
#include <stdint.h>

#define B_ 8
#define C_ 64
#define N_ 4096

// support[b][j][c] = (X^T W)  row-major in (j, c)
__device__ float g_support[B_ * N_ * C_];
__device__ float g_norms2[B_ * N_];
__device__ float g_R2[B_];

// ---------------- helpers ----------------
__device__ __forceinline__ uint32_t f2tf32(float x) {
    uint32_t u;
    asm("cvt.rna.tf32.f32 %0, %1;" : "=r"(u) : "f"(x));
    return u;
}
__device__ __forceinline__ float ex2f(float x) {
    float y;
    asm("ex2.approx.f32 %0, %1;" : "=f"(y) : "f"(x));
    return y;
}
// D += A(16x8) * B(8x8), tf32 inputs, fp32 accum (legacy tensor path, no 'a' target needed)
__device__ __forceinline__ void mma_tf32(float* d, const uint32_t* a, const uint32_t* b) {
    asm volatile(
        "mma.sync.aligned.m16n8k8.row.col.f32.tf32.tf32.f32 "
        "{%0,%1,%2,%3}, {%4,%5,%6,%7}, {%8,%9}, {%0,%1,%2,%3};"
        : "+f"(d[0]), "+f"(d[1]), "+f"(d[2]), "+f"(d[3])
        : "r"(a[0]), "r"(a[1]), "r"(a[2]), "r"(a[3]), "r"(b[0]), "r"(b[1]));
}

// ---------------- prep kernels ----------------
__global__ void init_kernel() {
    if (threadIdx.x < B_) g_R2[threadIdx.x] = 0.f;
}

__global__ __launch_bounds__(256) void norms_kernel(const float* __restrict__ x) {
    int b = blockIdx.y;
    int i = blockIdx.x * 256 + threadIdx.x;
    const float* xb = x + (size_t)b * C_ * N_;
    float s = 0.f;
#pragma unroll 8
    for (int c = 0; c < C_; c++) {
        float v = xb[(size_t)c * N_ + i];
        s = fmaf(v, v, s);
    }
    g_norms2[b * N_ + i] = s;
    float m = s;
#pragma unroll
    for (int off = 16; off > 0; off >>= 1)
        m = fmaxf(m, __shfl_xor_sync(0xffffffffu, m, off));
    __shared__ float wm[8];
    if ((threadIdx.x & 31) == 0) wm[threadIdx.x >> 5] = m;
    __syncthreads();
    if (threadIdx.x == 0) {
        float bm = wm[0];
#pragma unroll
        for (int k = 1; k < 8; k++) bm = fmaxf(bm, wm[k]);
        atomicMax((int*)&g_R2[b], __float_as_int(bm));  // positive floats: int-max valid
    }
}

// support[b, j, c] = sum_k x[b, k, j] * w[k, c]   (exact fp32)
__global__ __launch_bounds__(256) void support_kernel(const float* __restrict__ x,
                                                      const float* __restrict__ w) {
    __shared__ float ws[64 * 64];
    __shared__ float xs[64 * 64];
    const int b  = blockIdx.y;
    const int jb = blockIdx.x * 64;
    const int t  = threadIdx.x;
    const int tx = t & 15, ty = t >> 4;
    const float* xb = x + (size_t)b * C_ * N_;

    for (int idx = t; idx < 1024; idx += 256) {
        ((float4*)ws)[idx] = ((const float4*)w)[idx];
        int k = idx >> 4, f = idx & 15;
        ((float4*)xs)[idx] = *(const float4*)(xb + k * N_ + jb + 4 * f);
    }
    __syncthreads();

    float acc[4][4] = {};
#pragma unroll 8
    for (int k = 0; k < 64; k++) {
        float4 xv = *(float4*)(xs + k * 64 + 4 * ty);
        float4 wv = *(float4*)(ws + k * 64 + 4 * tx);
        float xa[4] = {xv.x, xv.y, xv.z, xv.w};
        float wa[4] = {wv.x, wv.y, wv.z, wv.w};
#pragma unroll
        for (int jj = 0; jj < 4; jj++)
#pragma unroll
            for (int cc = 0; cc < 4; cc++)
                acc[jj][cc] = fmaf(xa[jj], wa[cc], acc[jj][cc]);
    }
    float* sb = g_support + ((size_t)b * N_ + jb) * C_;
#pragma unroll
    for (int jj = 0; jj < 4; jj++) {
        float4 r = make_float4(acc[jj][0], acc[jj][1], acc[jj][2], acc[jj][3]);
        *(float4*)(sb + (4 * ty + jj) * C_ + 4 * tx) = r;
    }
}

// ---------------- fused attention (mma.sync tf32, tf32x3 for S) ----------------
#define QK_STR 136   // ≡8 (mod 32): conflict-free (t4-row, g-col) fragment gathers
#define P_STR  132   // ≡4 (mod 32): conflict-free (g-row, t4-col) gathers
#define V_STR  72    // ≡8 (mod 32)

#define OFF_QH 0
#define OFF_QL (OFF_QH + 64 * QK_STR)
#define OFF_KH (OFF_QL + 64 * QK_STR)
#define OFF_KL (OFF_KH + 64 * QK_STR)
#define OFF_P  OFF_KH                    // P (128*132=16896) overlays KH+KL (2*8704=17408)
#define OFF_V  (OFF_KL + 64 * QK_STR)
#define OFF_L  (OFF_V + 128 * V_STR)
#define SMEM_FLOATS (OFF_L + 256)
#define SMEM_BYTES  (SMEM_FLOATS * 4)

__global__ __launch_bounds__(256) void attn_kernel(const float* __restrict__ x,
                                                   float* __restrict__ out) {
    extern __shared__ float sm[];
    float* qh = sm + OFF_QH;
    float* ql = sm + OFF_QL;
    float* kh = sm + OFF_KH;
    float* kl = sm + OFF_KL;
    float* pbuf = sm + OFF_P;
    float* vs = sm + OFF_V;
    float* lpart = sm + OFF_L;

    const int tid = threadIdx.x, w = tid >> 5, lane = tid & 31;
    const int g = lane >> 2, t4 = lane & 3;
    const int b = blockIdx.y, qb = blockIdx.x * 128;
    const float* xb = x + (size_t)b * C_ * N_;
    const float* vbg = g_support + (size_t)b * N_ * C_;

    // S-gemm warp tile: rows r0..r0+31 (2 m-tiles), cols cb..cb+63 (8 n-chunks)
    const int r0 = (w & 3) * 32;
    const int cb = (w >> 2) * 64;
    // PV warp tile: rows pr0..pr0+15, cols 0..63
    const int pr0 = w * 16;

    // ---- stage Q hi/lo ----
    for (int idx = tid; idx < 2048; idx += 256) {
        int c = idx >> 5, f = (idx & 31) * 4;
        float4 v = *(const float4*)(xb + (size_t)c * N_ + qb + f);
        float h0 = __uint_as_float(f2tf32(v.x));
        float h1 = __uint_as_float(f2tf32(v.y));
        float h2 = __uint_as_float(f2tf32(v.z));
        float h3 = __uint_as_float(f2tf32(v.w));
        *(float4*)(qh + c * QK_STR + f) = make_float4(h0, h1, h2, h3);
        float l0 = __uint_as_float(f2tf32(v.x - h0));
        float l1 = __uint_as_float(f2tf32(v.y - h1));
        float l2 = __uint_as_float(f2tf32(v.z - h2));
        float l3 = __uint_as_float(f2tf32(v.w - h3));
        *(float4*)(ql + c * QK_STR + f) = make_float4(l0, l1, l2, l3);
    }

    // softmax shift (Cauchy-Schwarz bound): rows of this warp's S tile, in log2 units
    const float L2E = 1.4426950408889634f;
    const float R2 = g_R2[b];
    float mB2[4];
    mB2[0] = sqrtf(g_norms2[b * N_ + qb + r0 + g] * R2) * L2E;
    mB2[1] = sqrtf(g_norms2[b * N_ + qb + r0 + g + 8] * R2) * L2E;
    mB2[2] = sqrtf(g_norms2[b * N_ + qb + r0 + 16 + g] * R2) * L2E;
    mB2[3] = sqrtf(g_norms2[b * N_ + qb + r0 + 24 + g] * R2) * L2E;

    float ls[4] = {0.f, 0.f, 0.f, 0.f};
    float oacc[8][4] = {};

    for (int kt = 0; kt < N_; kt += 128) {
        // ---- stage K hi/lo ([c][j]) and V ([j][c]) ----
        for (int idx = tid; idx < 2048; idx += 256) {
            int c = idx >> 5, f = (idx & 31) * 4;
            float4 v = *(const float4*)(xb + (size_t)c * N_ + kt + f);
            float h0 = __uint_as_float(f2tf32(v.x));
            float h1 = __uint_as_float(f2tf32(v.y));
            float h2 = __uint_as_float(f2tf32(v.z));
            float h3 = __uint_as_float(f2tf32(v.w));
            *(float4*)(kh + c * QK_STR + f) = make_float4(h0, h1, h2, h3);
            float l0 = __uint_as_float(f2tf32(v.x - h0));
            float l1 = __uint_as_float(f2tf32(v.y - h1));
            float l2 = __uint_as_float(f2tf32(v.z - h2));
            float l3 = __uint_as_float(f2tf32(v.w - h3));
            *(float4*)(kl + c * QK_STR + f) = make_float4(l0, l1, l2, l3);
        }
        for (int idx = tid; idx < 2048; idx += 256) {
            int j = idx >> 4, f = (idx & 15) * 4;
            *(float4*)(vs + j * V_STR + f) = *(const float4*)(vbg + (size_t)(kt + j) * C_ + f);
        }
        __syncthreads();

        // ---- GEMM1: S = Qh·Kh + Qh·Kl + Ql·Kh (tf32x3) ----
        float sacc[2][8][4] = {};
#pragma unroll
        for (int kc = 0; kc < 8; kc++) {
            uint32_t ah[2][4], al[2][4];
            const float* q0 = qh + (kc * 8 + t4) * QK_STR;
            const float* q1 = qh + (kc * 8 + t4 + 4) * QK_STR;
            const float* p0 = ql + (kc * 8 + t4) * QK_STR;
            const float* p1 = ql + (kc * 8 + t4 + 4) * QK_STR;
#pragma unroll
            for (int mt = 0; mt < 2; mt++) {
                int rb = r0 + mt * 16;
                ah[mt][0] = __float_as_uint(q0[rb + g]);
                ah[mt][1] = __float_as_uint(q0[rb + g + 8]);
                ah[mt][2] = __float_as_uint(q1[rb + g]);
                ah[mt][3] = __float_as_uint(q1[rb + g + 8]);
                al[mt][0] = __float_as_uint(p0[rb + g]);
                al[mt][1] = __float_as_uint(p0[rb + g + 8]);
                al[mt][2] = __float_as_uint(p1[rb + g]);
                al[mt][3] = __float_as_uint(p1[rb + g + 8]);
            }
            const float* k0h = kh + (kc * 8 + t4) * QK_STR;
            const float* k1h = kh + (kc * 8 + t4 + 4) * QK_STR;
            const float* k0l = kl + (kc * 8 + t4) * QK_STR;
            const float* k1l = kl + (kc * 8 + t4 + 4) * QK_STR;
#pragma unroll
            for (int nc = 0; nc < 8; nc++) {
                int col = cb + nc * 8 + g;
                uint32_t bh[2], bl[2];
                bh[0] = __float_as_uint(k0h[col]);
                bh[1] = __float_as_uint(k1h[col]);
                bl[0] = __float_as_uint(k0l[col]);
                bl[1] = __float_as_uint(k1l[col]);
#pragma unroll
                for (int mt = 0; mt < 2; mt++) {
                    mma_tf32(sacc[mt][nc], ah[mt], bh);
                    mma_tf32(sacc[mt][nc], ah[mt], bl);
                    mma_tf32(sacc[mt][nc], al[mt], bh);
                }
            }
        }
        __syncthreads();   // all warps done reading kh/kl -> safe to overlay P

        // ---- P = exp(S - mh), row-sum partials, stage P ----
#pragma unroll
        for (int mt = 0; mt < 2; mt++) {
#pragma unroll
            for (int nc = 0; nc < 8; nc++) {
                float e0 = ex2f(fmaf(sacc[mt][nc][0], L2E, -mB2[mt * 2 + 0]));
                float e1 = ex2f(fmaf(sacc[mt][nc][1], L2E, -mB2[mt * 2 + 0]));
                float e2 = ex2f(fmaf(sacc[mt][nc][2], L2E, -mB2[mt * 2 + 1]));
                float e3 = ex2f(fmaf(sacc[mt][nc][3], L2E, -mB2[mt * 2 + 1]));
                ls[mt * 2 + 0] += e0 + e1;
                ls[mt * 2 + 1] += e2 + e3;
                int row = r0 + mt * 16 + g;
                int col = cb + nc * 8 + 2 * t4;
                *(float2*)(pbuf + row * P_STR + col) = make_float2(e0, e1);
                *(float2*)(pbuf + (row + 8) * P_STR + col) = make_float2(e2, e3);
            }
        }
        __syncthreads();   // P visible

        // ---- GEMM2: O += P · V ----
#pragma unroll
        for (int kc = 0; kc < 16; kc++) {
            uint32_t ap[4];
            ap[0] = __float_as_uint(pbuf[(pr0 + g) * P_STR + kc * 8 + t4]);
            ap[1] = __float_as_uint(pbuf[(pr0 + g + 8) * P_STR + kc * 8 + t4]);
            ap[2] = __float_as_uint(pbuf[(pr0 + g) * P_STR + kc * 8 + t4 + 4]);
            ap[3] = __float_as_uint(pbuf[(pr0 + g + 8) * P_STR + kc * 8 + t4 + 4]);
            const float* v0 = vs + (kc * 8 + t4) * V_STR;
            const float* v1 = vs + (kc * 8 + t4 + 4) * V_STR;
#pragma unroll
            for (int nc = 0; nc < 8; nc++) {
                uint32_t bv[2];
                bv[0] = __float_as_uint(v0[nc * 8 + g]);
                bv[1] = __float_as_uint(v1[nc * 8 + g]);
                mma_tf32(oacc[nc], ap, bv);
            }
        }
        __syncthreads();   // P/vs reads done before next stage overwrites
    }

    // ---- combine row sums ----
#pragma unroll
    for (int i = 0; i < 4; i++) {
        ls[i] += __shfl_xor_sync(0xffffffffu, ls[i], 1);
        ls[i] += __shfl_xor_sync(0xffffffffu, ls[i], 2);
    }
    if (t4 == 0) {
        int hb = (w >> 2) * 128;
        lpart[hb + r0 + g] = ls[0];
        lpart[hb + r0 + g + 8] = ls[1];
        lpart[hb + r0 + 16 + g] = ls[2];
        lpart[hb + r0 + 24 + g] = ls[3];
    }
    __syncthreads();

    // ---- epilogue: normalize, stage O[c][i] into qh, write + residual ----
    float inv0 = 1.f / (lpart[pr0 + g] + lpart[128 + pr0 + g]);
    float inv1 = 1.f / (lpart[pr0 + g + 8] + lpart[128 + pr0 + g + 8]);
#pragma unroll
    for (int nc = 0; nc < 8; nc++) {
        int c = nc * 8 + 2 * t4;
        qh[c * QK_STR + pr0 + g] = oacc[nc][0] * inv0;
        qh[(c + 1) * QK_STR + pr0 + g] = oacc[nc][1] * inv0;
        qh[c * QK_STR + pr0 + g + 8] = oacc[nc][2] * inv1;
        qh[(c + 1) * QK_STR + pr0 + g + 8] = oacc[nc][3] * inv1;
    }
    __syncthreads();
    float* ob = out + (size_t)b * C_ * N_;
    for (int idx = tid; idx < 2048; idx += 256) {
        int c = idx >> 5, f = (idx & 31) * 4;
        float4 o = *(float4*)(qh + c * QK_STR + f);
        float4 xr = *(const float4*)(xb + (size_t)c * N_ + qb + f);
        o.x += xr.x; o.y += xr.y; o.z += xr.z; o.w += xr.w;
        *(float4*)(ob + (size_t)c * N_ + qb + f) = o;
    }
}

extern "C" void kernel_launch(void* const* d_in, const int* in_sizes, int n_in,
                              void* d_out, int out_size) {
    const float* x = (const float*)d_in[0];   // [8, 64, 64, 64] fp32
    const float* w = (const float*)d_in[1];   // [64, 64] fp32
    float* out = (float*)d_out;

    init_kernel<<<1, 32>>>();
    norms_kernel<<<dim3(N_ / 256, B_), 256>>>(x);
    support_kernel<<<dim3(N_ / 64, B_), 256>>>(x, w);
    cudaFuncSetAttribute(attn_kernel, cudaFuncAttributeMaxDynamicSharedMemorySize, SMEM_BYTES);
    attn_kernel<<<dim3(N_ / 128, B_), 256, SMEM_BYTES>>>(x, out);
}